// round 10
// baseline (speedup 1.0000x reference)
#include <cuda_runtime.h>
#include <math.h>

// Problem constants
#define B_   512
#define V_   2
#define D_   128
#define M_   1024          // V*B
#define K_   15            // TOP_K
#define KMAX 50
#define INV_T 14.285714285714286f   // 1/0.07
#define NJT  16            // j-tiles in se_fused

// Scratch (static device globals)
__device__ unsigned g_Abf[M_ * 64];        // anchors packed bf16x2 [i][d/2]
__device__ unsigned g_Gbf[K_ * B_ * 64];   // neighbors packed bf16x2
__device__ float g_nA[M_];                 // ||A_i||^2 (fp32 exact)
__device__ float g_nG[K_ * B_];            // ||G_r||^2
__device__ float g_accp[2][M_ * B_];       // partial k-sums [grp][i][b]
__device__ float g_accpT[2][B_ * M_];      // partial k-sums transposed
__device__ float g_acc[M_ * B_];           // accB combined
__device__ float g_accT[B_ * M_];          // accB combined, transposed
__device__ float g_pm[NJT * M_];           // per-(jtile,row) local max
__device__ float g_ps[NJT * M_];           // per-(jtile,row) partial sumexp
__device__ float g_spos[M_];               // S[i][i^512]
__device__ float g_loss[M_];               // per-row loss

// ---------------------------------------------------------------------------
__device__ __forceinline__ unsigned pack_bf(float lo, float hi) {
    unsigned r;
    asm("cvt.rn.bf16x2.f32 %0, %1, %2;" : "=r"(r) : "f"(hi), "f"(lo));
    return r;
}
__device__ __forceinline__ float rsq_ap(float x) {
    float r; asm("rsqrt.approx.f32 %0, %1;" : "=f"(r) : "f"(x)); return r;
}
__device__ __forceinline__ float rcp_ap(float x) {
    float r; asm("rcp.approx.f32 %0, %1;" : "=f"(r) : "f"(x)); return r;
}
__device__ __forceinline__ float fdist(float sq) {
    float d = (sq > 0.f) ? sq * rsq_ap(sq) : 0.f;   // sqrt(sq) via rsqrt
    return (1.f + rcp_ap(1.f + d)) * INV_T;
}
__device__ __forceinline__ void mma_bf16(float c[4], const unsigned a[4],
                                         unsigned b0, unsigned b1) {
    asm volatile(
        "mma.sync.aligned.m16n8k16.row.col.f32.bf16.bf16.f32 "
        "{%0,%1,%2,%3}, {%4,%5,%6,%7}, {%8,%9}, {%0,%1,%2,%3};\n"
        : "+f"(c[0]), "+f"(c[1]), "+f"(c[2]), "+f"(c[3])
        : "r"(a[0]), "r"(a[1]), "r"(a[2]), "r"(a[3]), "r"(b0), "r"(b1));
}
__device__ __forceinline__ void ldsm_x4(unsigned r[4], unsigned addr) {
    asm volatile(
        "ldmatrix.sync.aligned.m8n8.x4.shared.b16 {%0,%1,%2,%3}, [%4];"
        : "=r"(r[0]), "=r"(r[1]), "=r"(r[2]), "=r"(r[3]) : "r"(addr));
}
__device__ __forceinline__ unsigned sm_u32(const void* p) {
    return (unsigned)__cvta_generic_to_shared(p);
}

// ---------------------------------------------------------------------------
// K1: anchors -> bf16 pack + exact fp32 norms, warp-per-row.
__global__ void __launch_bounds__(256) build_anchor(const float* __restrict__ features) {
    int w = threadIdx.x >> 5;
    int lane = threadIdx.x & 31;
    int i = blockIdx.x * 8 + w;
    int v = i >> 9;
    int b = i & (B_ - 1);
    float4 val = *(const float4*)&features[(b * V_ + v) * D_ + lane * 4];
    float s = val.x * val.x + val.y * val.y + val.z * val.z + val.w * val.w;
#pragma unroll
    for (int st = 16; st > 0; st >>= 1)
        s += __shfl_xor_sync(0xffffffffu, s, st);
    *(uint2*)&g_Abf[i * 64 + lane * 2] =
        make_uint2(pack_bf(val.x, val.y), pack_bf(val.z, val.w));
    if (lane == 0) g_nA[i] = s;
}

// K2: gather neighbors -> bf16 pack + norms, warp-per-row.
__global__ void __launch_bounds__(256) gather_neigh(const float* __restrict__ saved,
                             const int* __restrict__ indices,
                             const int* __restrict__ rks) {
    int w = threadIdx.x >> 5;
    int lane = threadIdx.x & 31;
    int r = blockIdx.x * 8 + w;
    int k = r / B_;
    int b = r - k * B_;
    int idx = rks[indices[b] * KMAX + k];
    float4 val = *(const float4*)&saved[(long long)idx * D_ + lane * 4];
    float s = val.x * val.x + val.y * val.y + val.z * val.z + val.w * val.w;
#pragma unroll
    for (int st = 16; st > 0; st >>= 1)
        s += __shfl_xor_sync(0xffffffffu, s, st);
    *(uint2*)&g_Gbf[r * 64 + lane * 2] =
        make_uint2(pack_bf(val.x, val.y), pack_bf(val.z, val.w));
    if (lane == 0) g_nG[r] = s;
}

// ---------------------------------------------------------------------------
// K3: partial accB over a k-group. Tile 64(i) x 64(b), grid z = 2 k-groups.
__global__ void __launch_bounds__(256, 2) pk_all() {
    __shared__ unsigned As[64 * 64];
    __shared__ unsigned Bs[2][64 * 64];

    int grp = blockIdx.z;
    int k0 = grp * 8;
    int kend = (grp == 0) ? 8 : K_;
    int i0 = blockIdx.y * 64;
    int b0 = blockIdx.x * 64;
    int tid = threadIdx.x;
    int lane = tid & 31, warp = tid >> 5;
    int wm = warp >> 1, wn = warp & 1;
    int g = lane >> 2, t4 = lane & 3;
    int l7 = lane & 7;

#pragma unroll
    for (int q = 0; q < 4; q++) {
        int idx = q * 256 + tid;
        int row = idx >> 4, c4 = idx & 15;
        uint4 v = *(const uint4*)&g_Abf[(i0 + row) * 64 + c4 * 4];
        *(uint4*)&As[row * 64 + ((c4 * 4) ^ ((row & 7) << 2))] = v;
    }

    unsigned swl = l7 << 2;
    unsigned aBase = sm_u32(As) + (wm * 16 + (lane & 15)) * 256;
    unsigned koA = (lane >> 4) << 2;
    unsigned bRow0 = wn * 32 + ((lane >> 4) & 1) * 8 + l7;
    unsigned koB = ((lane >> 3) & 1) << 2;
    unsigned bBase0 = sm_u32(Bs) + bRow0 * 256;
    unsigned bBase1 = bBase0 + 16 * 256;

    float fsum[4][4];
#pragma unroll
    for (int nt = 0; nt < 4; nt++)
#pragma unroll
        for (int q = 0; q < 4; q++) fsum[nt][q] = 0.f;

    uint4 pre[4];
    {
        const unsigned* Gb = g_Gbf + (k0 * B_ + b0) * 64;
#pragma unroll
        for (int q = 0; q < 4; q++) {
            int idx = q * 256 + tid;
            int row = idx >> 4, c4 = idx & 15;
            pre[q] = *(const uint4*)&Gb[row * 64 + c4 * 4];
        }
    }

    int cur = 0;
#pragma unroll 1
    for (int k = k0; k < kend; k++) {
#pragma unroll
        for (int q = 0; q < 4; q++) {
            int idx = q * 256 + tid;
            int row = idx >> 4, c4 = idx & 15;
            *(uint4*)&Bs[cur][row * 64 + ((c4 * 4) ^ ((row & 7) << 2))] = pre[q];
        }
        __syncthreads();

        if (k + 1 < kend) {
            const unsigned* Gb = g_Gbf + ((k + 1) * B_ + b0) * 64;
#pragma unroll
            for (int q = 0; q < 4; q++) {
                int idx = q * 256 + tid;
                int row = idx >> 4, c4 = idx & 15;
                pre[q] = *(const uint4*)&Gb[row * 64 + c4 * 4];
            }
        }

        float dot[4][4];
#pragma unroll
        for (int nt = 0; nt < 4; nt++)
#pragma unroll
            for (int q = 0; q < 4; q++) dot[nt][q] = 0.f;

        unsigned bcur = (unsigned)(cur * (64 * 64 * 4));
#pragma unroll
        for (int s = 0; s < 8; s++) {
            unsigned a[4], bb0[4], bb1[4];
            ldsm_x4(a, aBase + ((((unsigned)(s * 8) + koA) ^ swl) << 2));
            ldsm_x4(bb0, bBase0 + bcur + ((((unsigned)(s * 8) + koB) ^ swl) << 2));
            ldsm_x4(bb1, bBase1 + bcur + ((((unsigned)(s * 8) + koB) ^ swl) << 2));
            mma_bf16(dot[0], a, bb0[0], bb0[1]);
            mma_bf16(dot[1], a, bb0[2], bb0[3]);
            mma_bf16(dot[2], a, bb1[0], bb1[1]);
            mma_bf16(dot[3], a, bb1[2], bb1[3]);
        }

        int ri = i0 + wm * 16 + g;
        float na0 = g_nA[ri];
        float na1 = g_nA[ri + 8];
#pragma unroll
        for (int nt = 0; nt < 4; nt++) {
            int cb = b0 + wn * 32 + nt * 8 + 2 * t4;
            float ng0 = g_nG[k * B_ + cb];
            float ng1 = g_nG[k * B_ + cb + 1];
            float* dd = dot[nt];
            fsum[nt][0] += fdist(fmaxf(na0 + ng0 - 2.f * dd[0], 0.f));
            fsum[nt][1] += fdist(fmaxf(na0 + ng1 - 2.f * dd[1], 0.f));
            fsum[nt][2] += fdist(fmaxf(na1 + ng0 - 2.f * dd[2], 0.f));
            fsum[nt][3] += fdist(fmaxf(na1 + ng1 - 2.f * dd[3], 0.f));
        }
        cur ^= 1;
    }

    float* P  = g_accp[grp];
    float* PT = g_accpT[grp];
    int ri = i0 + wm * 16 + g;
#pragma unroll
    for (int nt = 0; nt < 4; nt++) {
        int cb = b0 + wn * 32 + nt * 8 + 2 * t4;
        *(float2*)&P[ri * B_ + cb] = make_float2(fsum[nt][0], fsum[nt][1]);
        *(float2*)&P[(ri + 8) * B_ + cb] = make_float2(fsum[nt][2], fsum[nt][3]);
        PT[cb * M_ + ri] = fsum[nt][0];
        PT[(cb + 1) * M_ + ri] = fsum[nt][1];
        PT[cb * M_ + ri + 8] = fsum[nt][2];
        PT[(cb + 1) * M_ + ri + 8] = fsum[nt][3];
    }
}

// ---------------------------------------------------------------------------
// K4: combine partials: acc = (p0 + p1) / 15 for both layouts.
__global__ void __launch_bounds__(256) acc_comb() {
    int e = blockIdx.x * 256 + threadIdx.x;       // float4 index, 131072 total
    const float inv = 1.f / (float)K_;
    const float4* p0 = (const float4*)g_accp[0];
    const float4* p1 = (const float4*)g_accp[1];
    float4 a = p0[e], b = p1[e];
    a.x = (a.x + b.x) * inv; a.y = (a.y + b.y) * inv;
    a.z = (a.z + b.z) * inv; a.w = (a.w + b.w) * inv;
    ((float4*)g_acc)[e] = a;
    const float4* q0 = (const float4*)g_accpT[0];
    const float4* q1 = (const float4*)g_accpT[1];
    float4 c = q0[e], d = q1[e];
    c.x = (c.x + d.x) * inv; c.y = (c.y + d.y) * inv;
    c.z = (c.z + d.z) * inv; c.w = (c.w + d.w) * inv;
    ((float4*)g_accT)[e] = c;
}

// ---------------------------------------------------------------------------
// K5: fused S + local softmax partials. Tile 64(i) x 64(j).
// Emits per-(row, jtile): local max + partial sumexp (diag excluded),
// and captures g_spos in the block where j0 == i0 ^ 512.
__global__ void __launch_bounds__(256, 2) se_fused() {
    __shared__ unsigned As[64 * 64];
    __shared__ unsigned Bs[64 * 64];
    __shared__ int srmax[64];
    __shared__ float sps[64][2];

    int i0 = blockIdx.y * 64;
    int j0 = blockIdx.x * 64;
    int tid = threadIdx.x;
    int lane = tid & 31, warp = tid >> 5;
    int wm = warp >> 1, wn = warp & 1;
    int g = lane >> 2, t4 = lane & 3;
    int l7 = lane & 7;

#pragma unroll
    for (int q = 0; q < 4; q++) {
        int idx = q * 256 + tid;
        int row = idx >> 4, c4 = idx & 15;
        uint4 va = *(const uint4*)&g_Abf[(i0 + row) * 64 + c4 * 4];
        *(uint4*)&As[row * 64 + ((c4 * 4) ^ ((row & 7) << 2))] = va;
        uint4 vb = *(const uint4*)&g_Abf[(j0 + row) * 64 + c4 * 4];
        *(uint4*)&Bs[row * 64 + ((c4 * 4) ^ ((row & 7) << 2))] = vb;
    }
    if (tid < 64) srmax[tid] = 0;
    __syncthreads();

    unsigned swl = l7 << 2;
    unsigned aBase = sm_u32(As) + (wm * 16 + (lane & 15)) * 256;
    unsigned koA = (lane >> 4) << 2;
    unsigned bRow0 = wn * 32 + ((lane >> 4) & 1) * 8 + l7;
    unsigned koB = ((lane >> 3) & 1) << 2;
    unsigned bBase0 = sm_u32(Bs) + bRow0 * 256;
    unsigned bBase1 = bBase0 + 16 * 256;

    float dot[4][4];
#pragma unroll
    for (int nt = 0; nt < 4; nt++)
#pragma unroll
        for (int q = 0; q < 4; q++) dot[nt][q] = 0.f;

#pragma unroll
    for (int s = 0; s < 8; s++) {
        unsigned a[4], bb0[4], bb1[4];
        ldsm_x4(a, aBase + ((((unsigned)(s * 8) + koA) ^ swl) << 2));
        ldsm_x4(bb0, bBase0 + ((((unsigned)(s * 8) + koB) ^ swl) << 2));
        ldsm_x4(bb1, bBase1 + ((((unsigned)(s * 8) + koB) ^ swl) << 2));
        mma_bf16(dot[0], a, bb0[0], bb0[1]);
        mma_bf16(dot[1], a, bb0[2], bb0[3]);
        mma_bf16(dot[2], a, bb1[0], bb1[1]);
        mma_bf16(dot[3], a, bb1[2], bb1[3]);
    }

    int lr0 = wm * 16 + g;            // local rows
    int lr1 = lr0 + 8;
    int ri = i0 + lr0;
    float na0 = g_nA[ri];
    float na1 = g_nA[ri + 8];
    int im0 = ri & (B_ - 1);
    int im1 = (ri + 8) & (B_ - 1);
    bool dblk = (i0 == j0);
    bool pblk = (j0 == (i0 ^ 512));

    float sv0[4][2], sv1[4][2];       // S values rows lr0 / lr1
    float m0 = 0.f, m1 = 0.f;
#pragma unroll
    for (int nt = 0; nt < 4; nt++) {
        int lc = wn * 32 + nt * 8 + 2 * t4;
        int cj = j0 + lc;
        float nb0 = g_nA[cj];
        float nb1 = g_nA[cj + 1];
        float* dd = dot[nt];
        float d00 = fdist(fmaxf(na0 + nb0 - 2.f * dd[0], 0.f));
        float d01 = fdist(fmaxf(na0 + nb1 - 2.f * dd[1], 0.f));
        float d10 = fdist(fmaxf(na1 + nb0 - 2.f * dd[2], 0.f));
        float d11 = fdist(fmaxf(na1 + nb1 - 2.f * dd[3], 0.f));
        int jm = cj & (B_ - 1);
        float2 af0 = *(const float2*)&g_acc[ri * B_ + jm];
        float2 af1 = *(const float2*)&g_acc[(ri + 8) * B_ + jm];
        float2 bf0 = *(const float2*)&g_accT[im0 * M_ + cj];
        float2 bf1 = *(const float2*)&g_accT[im1 * M_ + cj];
        sv0[nt][0] = sqrtf(af0.x * af0.x + bf0.x * bf0.x + d00 * d00);
        sv0[nt][1] = sqrtf(af0.y * af0.y + bf0.y * bf0.y + d01 * d01);
        sv1[nt][0] = sqrtf(af1.x * af1.x + bf1.x * bf1.x + d10 * d10);
        sv1[nt][1] = sqrtf(af1.y * af1.y + bf1.y * bf1.y + d11 * d11);
        m0 = fmaxf(m0, fmaxf(sv0[nt][0], sv0[nt][1]));
        m1 = fmaxf(m1, fmaxf(sv1[nt][0], sv1[nt][1]));
        if (pblk) {
            if (lc == lr0) g_spos[ri] = sv0[nt][0];
            if (lc + 1 == lr0) g_spos[ri] = sv0[nt][1];
            if (lc == lr1) g_spos[ri + 8] = sv1[nt][0];
            if (lc + 1 == lr1) g_spos[ri + 8] = sv1[nt][1];
        }
    }
    // block-local row max (exact, deterministic)
    m0 = fmaxf(m0, __shfl_xor_sync(0xffffffffu, m0, 1));
    m0 = fmaxf(m0, __shfl_xor_sync(0xffffffffu, m0, 2));
    m1 = fmaxf(m1, __shfl_xor_sync(0xffffffffu, m1, 1));
    m1 = fmaxf(m1, __shfl_xor_sync(0xffffffffu, m1, 2));
    if (t4 == 0) {
        atomicMax(&srmax[lr0], __float_as_int(m0));
        atomicMax(&srmax[lr1], __float_as_int(m1));
    }
    __syncthreads();
    float mr0 = __int_as_float(srmax[lr0]);
    float mr1 = __int_as_float(srmax[lr1]);

    float s0 = 0.f, s1 = 0.f;
#pragma unroll
    for (int nt = 0; nt < 4; nt++) {
        int lc = wn * 32 + nt * 8 + 2 * t4;
        float e00 = __expf(sv0[nt][0] - mr0);
        float e01 = __expf(sv0[nt][1] - mr0);
        float e10 = __expf(sv1[nt][0] - mr1);
        float e11 = __expf(sv1[nt][1] - mr1);
        if (dblk) {                     // exclude diagonal from sum
            if (lc == lr0) e00 = 0.f;
            if (lc + 1 == lr0) e01 = 0.f;
            if (lc == lr1) e10 = 0.f;
            if (lc + 1 == lr1) e11 = 0.f;
        }
        s0 += e00 + e01;
        s1 += e10 + e11;
    }
    // quad reduce (xor tree -> same grouping every run)
    s0 += __shfl_xor_sync(0xffffffffu, s0, 1);
    s0 += __shfl_xor_sync(0xffffffffu, s0, 2);
    s1 += __shfl_xor_sync(0xffffffffu, s1, 1);
    s1 += __shfl_xor_sync(0xffffffffu, s1, 2);
    if (t4 == 0) {
        sps[lr0][wn] = s0;
        sps[lr1][wn] = s1;
    }
    __syncthreads();
    if (tid < 64) {
        g_pm[blockIdx.x * M_ + i0 + tid] = __int_as_float(srmax[tid]);
        g_ps[blockIdx.x * M_ + i0 + tid] = sps[tid][0] + sps[tid][1];
    }
}

// ---------------------------------------------------------------------------
// K6: per-row lse combine over NJT tiles -> loss. Warp per row.
__global__ void __launch_bounds__(256) row_final() {
    int w = threadIdx.x >> 5;
    int lane = threadIdx.x & 31;
    int row = blockIdx.x * 8 + w;

    float ml = (lane < NJT) ? g_pm[lane * M_ + row] : -1e30f;
    float M = ml;
#pragma unroll
    for (int st = 16; st > 0; st >>= 1)
        M = fmaxf(M, __shfl_xor_sync(0xffffffffu, M, st));
    float p = (lane < NJT) ? g_ps[lane * M_ + row] * __expf(ml - M) : 0.f;
#pragma unroll
    for (int st = 16; st > 0; st >>= 1)
        p += __shfl_xor_sync(0xffffffffu, p, st);
    if (lane == 0) {
        float log_prob = (g_spos[row] - M) - logf(p);
        g_loss[row] = -log_prob;
    }
}

// K7: final mean
__global__ void __launch_bounds__(256) final_reduce(float* __restrict__ out) {
    int tid = threadIdx.x;
    __shared__ float red[256];
    float s = 0.f;
    for (int j = tid; j < M_; j += 256) s += g_loss[j];
    red[tid] = s;
    __syncthreads();
    for (int st = 128; st > 0; st >>= 1) {
        if (tid < st) red[tid] += red[tid + st];
        __syncthreads();
    }
    if (tid == 0) out[0] = red[0] * (1.f / (float)M_);
}

// ---------------------------------------------------------------------------
extern "C" void kernel_launch(void* const* d_in, const int* in_sizes, int n_in,
                              void* d_out, int out_size) {
    const float* features = (const float*)d_in[0];   // (512, 2, 128) f32
    const int*   indices  = (const int*)d_in[1];     // (512,) i32
    const float* saved    = (const float*)d_in[2];   // (100000, 128) f32
    const int*   rks      = (const int*)d_in[3];     // (100000, 50) i32
    float* out = (float*)d_out;

    build_anchor<<<M_ / 8, 256>>>(features);
    gather_neigh<<<(K_ * B_) / 8, 256>>>(saved, indices, rks);
    pk_all<<<dim3(B_ / 64, M_ / 64, 2), 256>>>();
    acc_comb<<<(M_ * B_ / 4) / 256, 256>>>();
    se_fused<<<dim3(M_ / 64, M_ / 64), 256>>>();
    row_final<<<M_ / 8, 256>>>();
    final_reduce<<<1, 256>>>(out);
}

// round 13
// speedup vs baseline: 1.0652x; 1.0652x over previous
#include <cuda_runtime.h>
#include <math.h>

// Problem constants
#define B_   512
#define V_   2
#define D_   128
#define M_   1024          // V*B
#define K_   15            // TOP_K
#define KMAX 50
#define INV_T 14.285714285714286f   // 1/0.07
#define NJT  16            // j-tiles in se_fused

// Scratch (static device globals)
__device__ unsigned g_Abf[M_ * 64];        // anchors packed bf16x2 [i][d/2]
__device__ unsigned g_Gbf[K_ * B_ * 64];   // neighbors packed bf16x2
__device__ float g_nA[M_];                 // ||A_i||^2 (fp32 exact)
__device__ float g_nG[K_ * B_];            // ||G_r||^2
__device__ float g_acc[M_ * B_];           // accB (red.add target)
__device__ float g_accT[B_ * M_];          // accB transposed (red.add target)
__device__ float g_pm[NJT * M_];           // per-(jtile,row) local max
__device__ float g_ps[NJT * M_];           // per-(jtile,row) partial sumexp
__device__ float g_spos[M_];               // S[i][i^512]
__device__ float g_loss[M_];               // per-row loss

// ---------------------------------------------------------------------------
__device__ __forceinline__ unsigned pack_bf(float lo, float hi) {
    unsigned r;
    asm("cvt.rn.bf16x2.f32 %0, %1, %2;" : "=r"(r) : "f"(hi), "f"(lo));
    return r;
}
__device__ __forceinline__ float rsq_ap(float x) {
    float r; asm("rsqrt.approx.f32 %0, %1;" : "=f"(r) : "f"(x)); return r;
}
__device__ __forceinline__ float rcp_ap(float x) {
    float r; asm("rcp.approx.f32 %0, %1;" : "=f"(r) : "f"(x)); return r;
}
__device__ __forceinline__ float fdist(float sq) {
    float d = (sq > 0.f) ? sq * rsq_ap(sq) : 0.f;   // sqrt(sq) via rsqrt
    return (1.f + rcp_ap(1.f + d)) * INV_T;
}
__device__ __forceinline__ void redadd(float* p, float v) {
    asm volatile("red.global.add.f32 [%0], %1;" :: "l"(p), "f"(v) : "memory");
}
__device__ __forceinline__ void mma_bf16(float c[4], const unsigned a[4],
                                         unsigned b0, unsigned b1) {
    asm volatile(
        "mma.sync.aligned.m16n8k16.row.col.f32.bf16.bf16.f32 "
        "{%0,%1,%2,%3}, {%4,%5,%6,%7}, {%8,%9}, {%0,%1,%2,%3};\n"
        : "+f"(c[0]), "+f"(c[1]), "+f"(c[2]), "+f"(c[3])
        : "r"(a[0]), "r"(a[1]), "r"(a[2]), "r"(a[3]), "r"(b0), "r"(b1));
}
__device__ __forceinline__ void ldsm_x4(unsigned r[4], unsigned addr) {
    asm volatile(
        "ldmatrix.sync.aligned.m8n8.x4.shared.b16 {%0,%1,%2,%3}, [%4];"
        : "=r"(r[0]), "=r"(r[1]), "=r"(r[2]), "=r"(r[3]) : "r"(addr));
}
__device__ __forceinline__ unsigned sm_u32(const void* p) {
    return (unsigned)__cvta_generic_to_shared(p);
}

// ---------------------------------------------------------------------------
// K1: anchors -> bf16 pack + exact fp32 norms, warp-per-row.
// Also zeroes g_acc/g_accT every replay (red.add targets).
__global__ void __launch_bounds__(256) build_anchor(const float* __restrict__ features) {
    int w = threadIdx.x >> 5;
    int lane = threadIdx.x & 31;
    int i = blockIdx.x * 8 + w;
    int v = i >> 9;
    int b = i & (B_ - 1);
    float4 val = *(const float4*)&features[(b * V_ + v) * D_ + lane * 4];
    float s = val.x * val.x + val.y * val.y + val.z * val.z + val.w * val.w;
#pragma unroll
    for (int st = 16; st > 0; st >>= 1)
        s += __shfl_xor_sync(0xffffffffu, s, st);
    *(uint2*)&g_Abf[i * 64 + lane * 2] =
        make_uint2(pack_bf(val.x, val.y), pack_bf(val.z, val.w));
    if (lane == 0) g_nA[i] = s;

    // zero the reduction targets: M_*B_ = 524288 floats = 131072 float4 each;
    // 128 blocks * 256 threads = 32768 lanes -> 4 float4 per lane per array.
    int t = blockIdx.x * 256 + threadIdx.x;      // 0..32767
    float4 z = make_float4(0.f, 0.f, 0.f, 0.f);
#pragma unroll
    for (int q = 0; q < 4; q++) {
        ((float4*)g_acc)[q * 32768 + t] = z;
        ((float4*)g_accT)[q * 32768 + t] = z;
    }
}

// K2: gather neighbors -> bf16 pack + norms, warp-per-row.
__global__ void __launch_bounds__(256) gather_neigh(const float* __restrict__ saved,
                             const int* __restrict__ indices,
                             const int* __restrict__ rks) {
    int w = threadIdx.x >> 5;
    int lane = threadIdx.x & 31;
    int r = blockIdx.x * 8 + w;
    int k = r / B_;
    int b = r - k * B_;
    int idx = rks[indices[b] * KMAX + k];
    float4 val = *(const float4*)&saved[(long long)idx * D_ + lane * 4];
    float s = val.x * val.x + val.y * val.y + val.z * val.z + val.w * val.w;
#pragma unroll
    for (int st = 16; st > 0; st >>= 1)
        s += __shfl_xor_sync(0xffffffffu, s, st);
    *(uint2*)&g_Gbf[r * 64 + lane * 2] =
        make_uint2(pack_bf(val.x, val.y), pack_bf(val.z, val.w));
    if (lane == 0) g_nG[r] = s;
}

// ---------------------------------------------------------------------------
// K3: partial accB over a k-group, red.add'ed (pre-scaled by 1/15) into
// g_acc/g_accT. Exactly 2 contributions per address onto 0.0 -> deterministic.
__global__ void __launch_bounds__(256, 2) pk_all() {
    __shared__ unsigned As[64 * 64];
    __shared__ unsigned Bs[2][64 * 64];

    int grp = blockIdx.z;
    int k0 = grp * 8;
    int kend = (grp == 0) ? 8 : K_;
    int i0 = blockIdx.y * 64;
    int b0 = blockIdx.x * 64;
    int tid = threadIdx.x;
    int lane = tid & 31, warp = tid >> 5;
    int wm = warp >> 1, wn = warp & 1;
    int g = lane >> 2, t4 = lane & 3;
    int l7 = lane & 7;

#pragma unroll
    for (int q = 0; q < 4; q++) {
        int idx = q * 256 + tid;
        int row = idx >> 4, c4 = idx & 15;
        uint4 v = *(const uint4*)&g_Abf[(i0 + row) * 64 + c4 * 4];
        *(uint4*)&As[row * 64 + ((c4 * 4) ^ ((row & 7) << 2))] = v;
    }

    unsigned swl = l7 << 2;
    unsigned aBase = sm_u32(As) + (wm * 16 + (lane & 15)) * 256;
    unsigned koA = (lane >> 4) << 2;
    unsigned bRow0 = wn * 32 + ((lane >> 4) & 1) * 8 + l7;
    unsigned koB = ((lane >> 3) & 1) << 2;
    unsigned bBase0 = sm_u32(Bs) + bRow0 * 256;
    unsigned bBase1 = bBase0 + 16 * 256;

    float fsum[4][4];
#pragma unroll
    for (int nt = 0; nt < 4; nt++)
#pragma unroll
        for (int q = 0; q < 4; q++) fsum[nt][q] = 0.f;

    uint4 pre[4];
    {
        const unsigned* Gb = g_Gbf + (k0 * B_ + b0) * 64;
#pragma unroll
        for (int q = 0; q < 4; q++) {
            int idx = q * 256 + tid;
            int row = idx >> 4, c4 = idx & 15;
            pre[q] = *(const uint4*)&Gb[row * 64 + c4 * 4];
        }
    }

    int cur = 0;
#pragma unroll 1
    for (int k = k0; k < kend; k++) {
#pragma unroll
        for (int q = 0; q < 4; q++) {
            int idx = q * 256 + tid;
            int row = idx >> 4, c4 = idx & 15;
            *(uint4*)&Bs[cur][row * 64 + ((c4 * 4) ^ ((row & 7) << 2))] = pre[q];
        }
        __syncthreads();

        if (k + 1 < kend) {
            const unsigned* Gb = g_Gbf + ((k + 1) * B_ + b0) * 64;
#pragma unroll
            for (int q = 0; q < 4; q++) {
                int idx = q * 256 + tid;
                int row = idx >> 4, c4 = idx & 15;
                pre[q] = *(const uint4*)&Gb[row * 64 + c4 * 4];
            }
        }

        float dot[4][4];
#pragma unroll
        for (int nt = 0; nt < 4; nt++)
#pragma unroll
            for (int q = 0; q < 4; q++) dot[nt][q] = 0.f;

        unsigned bcur = (unsigned)(cur * (64 * 64 * 4));
#pragma unroll
        for (int s = 0; s < 8; s++) {
            unsigned a[4], bb0[4], bb1[4];
            ldsm_x4(a, aBase + ((((unsigned)(s * 8) + koA) ^ swl) << 2));
            ldsm_x4(bb0, bBase0 + bcur + ((((unsigned)(s * 8) + koB) ^ swl) << 2));
            ldsm_x4(bb1, bBase1 + bcur + ((((unsigned)(s * 8) + koB) ^ swl) << 2));
            mma_bf16(dot[0], a, bb0[0], bb0[1]);
            mma_bf16(dot[1], a, bb0[2], bb0[3]);
            mma_bf16(dot[2], a, bb1[0], bb1[1]);
            mma_bf16(dot[3], a, bb1[2], bb1[3]);
        }

        int ri = i0 + wm * 16 + g;
        float na0 = g_nA[ri];
        float na1 = g_nA[ri + 8];
#pragma unroll
        for (int nt = 0; nt < 4; nt++) {
            int cb = b0 + wn * 32 + nt * 8 + 2 * t4;
            float ng0 = g_nG[k * B_ + cb];
            float ng1 = g_nG[k * B_ + cb + 1];
            float* dd = dot[nt];
            fsum[nt][0] += fdist(fmaxf(na0 + ng0 - 2.f * dd[0], 0.f));
            fsum[nt][1] += fdist(fmaxf(na0 + ng1 - 2.f * dd[1], 0.f));
            fsum[nt][2] += fdist(fmaxf(na1 + ng0 - 2.f * dd[2], 0.f));
            fsum[nt][3] += fdist(fmaxf(na1 + ng1 - 2.f * dd[3], 0.f));
        }
        cur ^= 1;
    }

    const float inv = 1.f / (float)K_;
    int ri = i0 + wm * 16 + g;
#pragma unroll
    for (int nt = 0; nt < 4; nt++) {
        int cb = b0 + wn * 32 + nt * 8 + 2 * t4;
        float v00 = fsum[nt][0] * inv, v01 = fsum[nt][1] * inv;
        float v10 = fsum[nt][2] * inv, v11 = fsum[nt][3] * inv;
        redadd(&g_acc[ri * B_ + cb], v00);
        redadd(&g_acc[ri * B_ + cb + 1], v01);
        redadd(&g_acc[(ri + 8) * B_ + cb], v10);
        redadd(&g_acc[(ri + 8) * B_ + cb + 1], v11);
        redadd(&g_accT[cb * M_ + ri], v00);
        redadd(&g_accT[(cb + 1) * M_ + ri], v01);
        redadd(&g_accT[cb * M_ + ri + 8], v10);
        redadd(&g_accT[(cb + 1) * M_ + ri + 8], v11);
    }
}

// ---------------------------------------------------------------------------
// K5: fused S + local softmax partials. Tile 64(i) x 64(j).
__global__ void __launch_bounds__(256, 2) se_fused() {
    __shared__ unsigned As[64 * 64];
    __shared__ unsigned Bs[64 * 64];
    __shared__ int srmax[64];
    __shared__ float sps[64][2];

    int i0 = blockIdx.y * 64;
    int j0 = blockIdx.x * 64;
    int tid = threadIdx.x;
    int lane = tid & 31, warp = tid >> 5;
    int wm = warp >> 1, wn = warp & 1;
    int g = lane >> 2, t4 = lane & 3;
    int l7 = lane & 7;

#pragma unroll
    for (int q = 0; q < 4; q++) {
        int idx = q * 256 + tid;
        int row = idx >> 4, c4 = idx & 15;
        uint4 va = *(const uint4*)&g_Abf[(i0 + row) * 64 + c4 * 4];
        *(uint4*)&As[row * 64 + ((c4 * 4) ^ ((row & 7) << 2))] = va;
        uint4 vb = *(const uint4*)&g_Abf[(j0 + row) * 64 + c4 * 4];
        *(uint4*)&Bs[row * 64 + ((c4 * 4) ^ ((row & 7) << 2))] = vb;
    }
    if (tid < 64) srmax[tid] = 0;
    __syncthreads();

    unsigned swl = l7 << 2;
    unsigned aBase = sm_u32(As) + (wm * 16 + (lane & 15)) * 256;
    unsigned koA = (lane >> 4) << 2;
    unsigned bRow0 = wn * 32 + ((lane >> 4) & 1) * 8 + l7;
    unsigned koB = ((lane >> 3) & 1) << 2;
    unsigned bBase0 = sm_u32(Bs) + bRow0 * 256;
    unsigned bBase1 = bBase0 + 16 * 256;

    float dot[4][4];
#pragma unroll
    for (int nt = 0; nt < 4; nt++)
#pragma unroll
        for (int q = 0; q < 4; q++) dot[nt][q] = 0.f;

#pragma unroll
    for (int s = 0; s < 8; s++) {
        unsigned a[4], bb0[4], bb1[4];
        ldsm_x4(a, aBase + ((((unsigned)(s * 8) + koA) ^ swl) << 2));
        ldsm_x4(bb0, bBase0 + ((((unsigned)(s * 8) + koB) ^ swl) << 2));
        ldsm_x4(bb1, bBase1 + ((((unsigned)(s * 8) + koB) ^ swl) << 2));
        mma_bf16(dot[0], a, bb0[0], bb0[1]);
        mma_bf16(dot[1], a, bb0[2], bb0[3]);
        mma_bf16(dot[2], a, bb1[0], bb1[1]);
        mma_bf16(dot[3], a, bb1[2], bb1[3]);
    }

    int lr0 = wm * 16 + g;            // local rows
    int lr1 = lr0 + 8;
    int ri = i0 + lr0;
    float na0 = g_nA[ri];
    float na1 = g_nA[ri + 8];
    int im0 = ri & (B_ - 1);
    int im1 = (ri + 8) & (B_ - 1);
    bool dblk = (i0 == j0);
    bool pblk = (j0 == (i0 ^ 512));

    float sv0[4][2], sv1[4][2];       // S values rows lr0 / lr1
    float m0 = 0.f, m1 = 0.f;
#pragma unroll
    for (int nt = 0; nt < 4; nt++) {
        int lc = wn * 32 + nt * 8 + 2 * t4;
        int cj = j0 + lc;
        float nb0 = g_nA[cj];
        float nb1 = g_nA[cj + 1];
        float* dd = dot[nt];
        float d00 = fdist(fmaxf(na0 + nb0 - 2.f * dd[0], 0.f));
        float d01 = fdist(fmaxf(na0 + nb1 - 2.f * dd[1], 0.f));
        float d10 = fdist(fmaxf(na1 + nb0 - 2.f * dd[2], 0.f));
        float d11 = fdist(fmaxf(na1 + nb1 - 2.f * dd[3], 0.f));
        int jm = cj & (B_ - 1);
        float2 af0 = *(const float2*)&g_acc[ri * B_ + jm];
        float2 af1 = *(const float2*)&g_acc[(ri + 8) * B_ + jm];
        float2 bf0 = *(const float2*)&g_accT[im0 * M_ + cj];
        float2 bf1 = *(const float2*)&g_accT[im1 * M_ + cj];
        float q00 = af0.x * af0.x + bf0.x * bf0.x + d00 * d00;
        float q01 = af0.y * af0.y + bf0.y * bf0.y + d01 * d01;
        float q10 = af1.x * af1.x + bf1.x * bf1.x + d10 * d10;
        float q11 = af1.y * af1.y + bf1.y * bf1.y + d11 * d11;
        sv0[nt][0] = q00 * rsq_ap(q00);    // sqrt; q >= d^2 > 200, never 0
        sv0[nt][1] = q01 * rsq_ap(q01);
        sv1[nt][0] = q10 * rsq_ap(q10);
        sv1[nt][1] = q11 * rsq_ap(q11);
        m0 = fmaxf(m0, fmaxf(sv0[nt][0], sv0[nt][1]));
        m1 = fmaxf(m1, fmaxf(sv1[nt][0], sv1[nt][1]));
        if (pblk) {
            if (lc == lr0) g_spos[ri] = sv0[nt][0];
            if (lc + 1 == lr0) g_spos[ri] = sv0[nt][1];
            if (lc == lr1) g_spos[ri + 8] = sv1[nt][0];
            if (lc + 1 == lr1) g_spos[ri + 8] = sv1[nt][1];
        }
    }
    // block-local row max (exact, deterministic)
    m0 = fmaxf(m0, __shfl_xor_sync(0xffffffffu, m0, 1));
    m0 = fmaxf(m0, __shfl_xor_sync(0xffffffffu, m0, 2));
    m1 = fmaxf(m1, __shfl_xor_sync(0xffffffffu, m1, 1));
    m1 = fmaxf(m1, __shfl_xor_sync(0xffffffffu, m1, 2));
    if (t4 == 0) {
        atomicMax(&srmax[lr0], __float_as_int(m0));
        atomicMax(&srmax[lr1], __float_as_int(m1));
    }
    __syncthreads();
    float mr0 = __int_as_float(srmax[lr0]);
    float mr1 = __int_as_float(srmax[lr1]);

    float s0 = 0.f, s1 = 0.f;
#pragma unroll
    for (int nt = 0; nt < 4; nt++) {
        int lc = wn * 32 + nt * 8 + 2 * t4;
        float e00 = __expf(sv0[nt][0] - mr0);
        float e01 = __expf(sv0[nt][1] - mr0);
        float e10 = __expf(sv1[nt][0] - mr1);
        float e11 = __expf(sv1[nt][1] - mr1);
        if (dblk) {                     // exclude diagonal from sum
            if (lc == lr0) e00 = 0.f;
            if (lc + 1 == lr0) e01 = 0.f;
            if (lc == lr1) e10 = 0.f;
            if (lc + 1 == lr1) e11 = 0.f;
        }
        s0 += e00 + e01;
        s1 += e10 + e11;
    }
    // quad reduce (xor tree -> same grouping every run)
    s0 += __shfl_xor_sync(0xffffffffu, s0, 1);
    s0 += __shfl_xor_sync(0xffffffffu, s0, 2);
    s1 += __shfl_xor_sync(0xffffffffu, s1, 1);
    s1 += __shfl_xor_sync(0xffffffffu, s1, 2);
    if (t4 == 0) {
        sps[lr0][wn] = s0;
        sps[lr1][wn] = s1;
    }
    __syncthreads();
    if (tid < 64) {
        g_pm[blockIdx.x * M_ + i0 + tid] = __int_as_float(srmax[tid]);
        g_ps[blockIdx.x * M_ + i0 + tid] = sps[tid][0] + sps[tid][1];
    }
}

// ---------------------------------------------------------------------------
// K6: per-row lse combine over NJT tiles -> loss. Warp per row.
__global__ void __launch_bounds__(256) row_final() {
    int w = threadIdx.x >> 5;
    int lane = threadIdx.x & 31;
    int row = blockIdx.x * 8 + w;

    float ml = (lane < NJT) ? g_pm[lane * M_ + row] : -1e30f;
    float M = ml;
#pragma unroll
    for (int st = 16; st > 0; st >>= 1)
        M = fmaxf(M, __shfl_xor_sync(0xffffffffu, M, st));
    float p = (lane < NJT) ? g_ps[lane * M_ + row] * __expf(ml - M) : 0.f;
#pragma unroll
    for (int st = 16; st > 0; st >>= 1)
        p += __shfl_xor_sync(0xffffffffu, p, st);
    if (lane == 0) {
        float log_prob = (g_spos[row] - M) - logf(p);
        g_loss[row] = -log_prob;
    }
}

// K7: final mean
__global__ void __launch_bounds__(256) final_reduce(float* __restrict__ out) {
    int tid = threadIdx.x;
    __shared__ float red[256];
    float s = 0.f;
    for (int j = tid; j < M_; j += 256) s += g_loss[j];
    red[tid] = s;
    __syncthreads();
    for (int st = 128; st > 0; st >>= 1) {
        if (tid < st) red[tid] += red[tid + st];
        __syncthreads();
    }
    if (tid == 0) out[0] = red[0] * (1.f / (float)M_);
}

// ---------------------------------------------------------------------------
extern "C" void kernel_launch(void* const* d_in, const int* in_sizes, int n_in,
                              void* d_out, int out_size) {
    const float* features = (const float*)d_in[0];   // (512, 2, 128) f32
    const int*   indices  = (const int*)d_in[1];     // (512,) i32
    const float* saved    = (const float*)d_in[2];   // (100000, 128) f32
    const int*   rks      = (const int*)d_in[3];     // (100000, 50) i32
    float* out = (float*)d_out;

    build_anchor<<<M_ / 8, 256>>>(features);
    gather_neigh<<<(K_ * B_) / 8, 256>>>(saved, indices, rks);
    pk_all<<<dim3(B_ / 64, M_ / 64, 2), 256>>>();
    se_fused<<<dim3(M_ / 64, M_ / 64), 256>>>();
    row_final<<<M_ / 8, 256>>>();
    final_reduce<<<1, 256>>>(out);
}

// round 14
// speedup vs baseline: 1.1100x; 1.0421x over previous
#include <cuda_runtime.h>
#include <math.h>

// Problem constants
#define B_   512
#define V_   2
#define D_   128
#define M_   1024          // V*B
#define K_   15            // TOP_K
#define KMAX 50
#define INV_T 14.285714285714286f   // 1/0.07
#define NJT  16            // j-tiles in se_fused

// Scratch (static device globals)
__device__ unsigned g_Abf[M_ * 64];        // anchors packed bf16x2 [i][d/2]
__device__ unsigned g_Gbf[K_ * B_ * 64];   // neighbors packed bf16x2
__device__ float g_nA[M_];                 // ||A_i||^2 (fp32 exact)
__device__ float g_nG[K_ * B_];            // ||G_r||^2
__device__ float g_acc[M_ * B_];           // accB (red.add target)
__device__ float g_accT[B_ * M_];          // accB transposed (red.add target)
__device__ float g_pm[NJT * M_];           // per-(jtile,row) local max
__device__ float g_ps[NJT * M_];           // per-(jtile,row) partial sumexp
__device__ float g_spos[M_];               // S[i][i^512]

// ---------------------------------------------------------------------------
__device__ __forceinline__ unsigned pack_bf(float lo, float hi) {
    unsigned r;
    asm("cvt.rn.bf16x2.f32 %0, %1, %2;" : "=r"(r) : "f"(hi), "f"(lo));
    return r;
}
__device__ __forceinline__ float rsq_ap(float x) {
    float r; asm("rsqrt.approx.f32 %0, %1;" : "=f"(r) : "f"(x)); return r;
}
__device__ __forceinline__ float rcp_ap(float x) {
    float r; asm("rcp.approx.f32 %0, %1;" : "=f"(r) : "f"(x)); return r;
}
__device__ __forceinline__ float fdist(float sq) {
    float d = (sq > 0.f) ? sq * rsq_ap(sq) : 0.f;   // sqrt(sq) via rsqrt
    return (1.f + rcp_ap(1.f + d)) * INV_T;
}
__device__ __forceinline__ void redadd(float* p, float v) {
    asm volatile("red.global.add.f32 [%0], %1;" :: "l"(p), "f"(v) : "memory");
}
__device__ __forceinline__ void mma_bf16(float c[4], const unsigned a[4],
                                         unsigned b0, unsigned b1) {
    asm volatile(
        "mma.sync.aligned.m16n8k16.row.col.f32.bf16.bf16.f32 "
        "{%0,%1,%2,%3}, {%4,%5,%6,%7}, {%8,%9}, {%0,%1,%2,%3};\n"
        : "+f"(c[0]), "+f"(c[1]), "+f"(c[2]), "+f"(c[3])
        : "r"(a[0]), "r"(a[1]), "r"(a[2]), "r"(a[3]), "r"(b0), "r"(b1));
}
__device__ __forceinline__ void ldsm_x4(unsigned r[4], unsigned addr) {
    asm volatile(
        "ldmatrix.sync.aligned.m8n8.x4.shared.b16 {%0,%1,%2,%3}, [%4];"
        : "=r"(r[0]), "=r"(r[1]), "=r"(r[2]), "=r"(r[3]) : "r"(addr));
}
__device__ __forceinline__ unsigned sm_u32(const void* p) {
    return (unsigned)__cvta_generic_to_shared(p);
}

// ---------------------------------------------------------------------------
// K1: merged setup. Blocks 0..127: anchors (pack + norms) + zero acc targets.
// Blocks 128..1087: neighbor gather (pack + norms). Warp-per-row both halves.
__global__ void __launch_bounds__(256) setup(const float* __restrict__ features,
                                             const float* __restrict__ saved,
                                             const int* __restrict__ indices,
                                             const int* __restrict__ rks) {
    int w = threadIdx.x >> 5;
    int lane = threadIdx.x & 31;

    if (blockIdx.x < 128) {
        int i = blockIdx.x * 8 + w;          // anchor row
        int v = i >> 9;
        int b = i & (B_ - 1);
        float4 val = *(const float4*)&features[(b * V_ + v) * D_ + lane * 4];
        float s = val.x * val.x + val.y * val.y + val.z * val.z + val.w * val.w;
#pragma unroll
        for (int st = 16; st > 0; st >>= 1)
            s += __shfl_xor_sync(0xffffffffu, s, st);
        *(uint2*)&g_Abf[i * 64 + lane * 2] =
            make_uint2(pack_bf(val.x, val.y), pack_bf(val.z, val.w));
        if (lane == 0) g_nA[i] = s;

        // zero reduction targets: 131072 float4 each; 32768 lanes -> 4 each
        int t = blockIdx.x * 256 + threadIdx.x;
        float4 z = make_float4(0.f, 0.f, 0.f, 0.f);
#pragma unroll
        for (int q = 0; q < 4; q++) {
            ((float4*)g_acc)[q * 32768 + t] = z;
            ((float4*)g_accT)[q * 32768 + t] = z;
        }
    } else {
        int r = (blockIdx.x - 128) * 8 + w;  // neighbor row 0..K_*B_-1
        int k = r / B_;
        int b = r - k * B_;
        int idx = rks[indices[b] * KMAX + k];
        float4 val = *(const float4*)&saved[(long long)idx * D_ + lane * 4];
        float s = val.x * val.x + val.y * val.y + val.z * val.z + val.w * val.w;
#pragma unroll
        for (int st = 16; st > 0; st >>= 1)
            s += __shfl_xor_sync(0xffffffffu, s, st);
        *(uint2*)&g_Gbf[r * 64 + lane * 2] =
            make_uint2(pack_bf(val.x, val.y), pack_bf(val.z, val.w));
        if (lane == 0) g_nG[r] = s;
    }
}

// ---------------------------------------------------------------------------
// K2: partial accB over a k-group, red.add'ed (pre-scaled by 1/15) into
// g_acc/g_accT. Exactly 2 contributions per address onto 0.0 -> deterministic.
__global__ void __launch_bounds__(256, 2) pk_all() {
    __shared__ unsigned As[64 * 64];
    __shared__ unsigned Bs[2][64 * 64];

    int grp = blockIdx.z;
    int k0 = grp * 8;
    int kend = (grp == 0) ? 8 : K_;
    int i0 = blockIdx.y * 64;
    int b0 = blockIdx.x * 64;
    int tid = threadIdx.x;
    int lane = tid & 31, warp = tid >> 5;
    int wm = warp >> 1, wn = warp & 1;
    int g = lane >> 2, t4 = lane & 3;
    int l7 = lane & 7;

#pragma unroll
    for (int q = 0; q < 4; q++) {
        int idx = q * 256 + tid;
        int row = idx >> 4, c4 = idx & 15;
        uint4 v = *(const uint4*)&g_Abf[(i0 + row) * 64 + c4 * 4];
        *(uint4*)&As[row * 64 + ((c4 * 4) ^ ((row & 7) << 2))] = v;
    }

    unsigned swl = l7 << 2;
    unsigned aBase = sm_u32(As) + (wm * 16 + (lane & 15)) * 256;
    unsigned koA = (lane >> 4) << 2;
    unsigned bRow0 = wn * 32 + ((lane >> 4) & 1) * 8 + l7;
    unsigned koB = ((lane >> 3) & 1) << 2;
    unsigned bBase0 = sm_u32(Bs) + bRow0 * 256;
    unsigned bBase1 = bBase0 + 16 * 256;

    float fsum[4][4];
#pragma unroll
    for (int nt = 0; nt < 4; nt++)
#pragma unroll
        for (int q = 0; q < 4; q++) fsum[nt][q] = 0.f;

    uint4 pre[4];
    {
        const unsigned* Gb = g_Gbf + (k0 * B_ + b0) * 64;
#pragma unroll
        for (int q = 0; q < 4; q++) {
            int idx = q * 256 + tid;
            int row = idx >> 4, c4 = idx & 15;
            pre[q] = *(const uint4*)&Gb[row * 64 + c4 * 4];
        }
    }

    int cur = 0;
#pragma unroll 1
    for (int k = k0; k < kend; k++) {
#pragma unroll
        for (int q = 0; q < 4; q++) {
            int idx = q * 256 + tid;
            int row = idx >> 4, c4 = idx & 15;
            *(uint4*)&Bs[cur][row * 64 + ((c4 * 4) ^ ((row & 7) << 2))] = pre[q];
        }
        __syncthreads();

        if (k + 1 < kend) {
            const unsigned* Gb = g_Gbf + ((k + 1) * B_ + b0) * 64;
#pragma unroll
            for (int q = 0; q < 4; q++) {
                int idx = q * 256 + tid;
                int row = idx >> 4, c4 = idx & 15;
                pre[q] = *(const uint4*)&Gb[row * 64 + c4 * 4];
            }
        }

        float dot[4][4];
#pragma unroll
        for (int nt = 0; nt < 4; nt++)
#pragma unroll
            for (int q = 0; q < 4; q++) dot[nt][q] = 0.f;

        unsigned bcur = (unsigned)(cur * (64 * 64 * 4));
#pragma unroll
        for (int s = 0; s < 8; s++) {
            unsigned a[4], bb0[4], bb1[4];
            ldsm_x4(a, aBase + ((((unsigned)(s * 8) + koA) ^ swl) << 2));
            ldsm_x4(bb0, bBase0 + bcur + ((((unsigned)(s * 8) + koB) ^ swl) << 2));
            ldsm_x4(bb1, bBase1 + bcur + ((((unsigned)(s * 8) + koB) ^ swl) << 2));
            mma_bf16(dot[0], a, bb0[0], bb0[1]);
            mma_bf16(dot[1], a, bb0[2], bb0[3]);
            mma_bf16(dot[2], a, bb1[0], bb1[1]);
            mma_bf16(dot[3], a, bb1[2], bb1[3]);
        }

        int ri = i0 + wm * 16 + g;
        float na0 = g_nA[ri];
        float na1 = g_nA[ri + 8];
#pragma unroll
        for (int nt = 0; nt < 4; nt++) {
            int cb = b0 + wn * 32 + nt * 8 + 2 * t4;
            float ng0 = g_nG[k * B_ + cb];
            float ng1 = g_nG[k * B_ + cb + 1];
            float* dd = dot[nt];
            fsum[nt][0] += fdist(fmaxf(na0 + ng0 - 2.f * dd[0], 0.f));
            fsum[nt][1] += fdist(fmaxf(na0 + ng1 - 2.f * dd[1], 0.f));
            fsum[nt][2] += fdist(fmaxf(na1 + ng0 - 2.f * dd[2], 0.f));
            fsum[nt][3] += fdist(fmaxf(na1 + ng1 - 2.f * dd[3], 0.f));
        }
        cur ^= 1;
    }

    const float inv = 1.f / (float)K_;
    int ri = i0 + wm * 16 + g;
#pragma unroll
    for (int nt = 0; nt < 4; nt++) {
        int cb = b0 + wn * 32 + nt * 8 + 2 * t4;
        float v00 = fsum[nt][0] * inv, v01 = fsum[nt][1] * inv;
        float v10 = fsum[nt][2] * inv, v11 = fsum[nt][3] * inv;
        redadd(&g_acc[ri * B_ + cb], v00);
        redadd(&g_acc[ri * B_ + cb + 1], v01);
        redadd(&g_acc[(ri + 8) * B_ + cb], v10);
        redadd(&g_acc[(ri + 8) * B_ + cb + 1], v11);
        redadd(&g_accT[cb * M_ + ri], v00);
        redadd(&g_accT[(cb + 1) * M_ + ri], v01);
        redadd(&g_accT[cb * M_ + ri + 8], v10);
        redadd(&g_accT[(cb + 1) * M_ + ri + 8], v11);
    }
}

// ---------------------------------------------------------------------------
// K3: fused S + local softmax partials. Tile 64(i) x 64(j).
__global__ void __launch_bounds__(256, 2) se_fused() {
    __shared__ unsigned As[64 * 64];
    __shared__ unsigned Bs[64 * 64];
    __shared__ int srmax[64];
    __shared__ float sps[64][2];

    int i0 = blockIdx.y * 64;
    int j0 = blockIdx.x * 64;
    int tid = threadIdx.x;
    int lane = tid & 31, warp = tid >> 5;
    int wm = warp >> 1, wn = warp & 1;
    int g = lane >> 2, t4 = lane & 3;
    int l7 = lane & 7;

#pragma unroll
    for (int q = 0; q < 4; q++) {
        int idx = q * 256 + tid;
        int row = idx >> 4, c4 = idx & 15;
        uint4 va = *(const uint4*)&g_Abf[(i0 + row) * 64 + c4 * 4];
        *(uint4*)&As[row * 64 + ((c4 * 4) ^ ((row & 7) << 2))] = va;
        uint4 vb = *(const uint4*)&g_Abf[(j0 + row) * 64 + c4 * 4];
        *(uint4*)&Bs[row * 64 + ((c4 * 4) ^ ((row & 7) << 2))] = vb;
    }
    if (tid < 64) srmax[tid] = 0;
    __syncthreads();

    unsigned swl = l7 << 2;
    unsigned aBase = sm_u32(As) + (wm * 16 + (lane & 15)) * 256;
    unsigned koA = (lane >> 4) << 2;
    unsigned bRow0 = wn * 32 + ((lane >> 4) & 1) * 8 + l7;
    unsigned koB = ((lane >> 3) & 1) << 2;
    unsigned bBase0 = sm_u32(Bs) + bRow0 * 256;
    unsigned bBase1 = bBase0 + 16 * 256;

    float dot[4][4];
#pragma unroll
    for (int nt = 0; nt < 4; nt++)
#pragma unroll
        for (int q = 0; q < 4; q++) dot[nt][q] = 0.f;

#pragma unroll
    for (int s = 0; s < 8; s++) {
        unsigned a[4], bb0[4], bb1[4];
        ldsm_x4(a, aBase + ((((unsigned)(s * 8) + koA) ^ swl) << 2));
        ldsm_x4(bb0, bBase0 + ((((unsigned)(s * 8) + koB) ^ swl) << 2));
        ldsm_x4(bb1, bBase1 + ((((unsigned)(s * 8) + koB) ^ swl) << 2));
        mma_bf16(dot[0], a, bb0[0], bb0[1]);
        mma_bf16(dot[1], a, bb0[2], bb0[3]);
        mma_bf16(dot[2], a, bb1[0], bb1[1]);
        mma_bf16(dot[3], a, bb1[2], bb1[3]);
    }

    int lr0 = wm * 16 + g;            // local rows
    int lr1 = lr0 + 8;
    int ri = i0 + lr0;
    float na0 = g_nA[ri];
    float na1 = g_nA[ri + 8];
    int im0 = ri & (B_ - 1);
    int im1 = (ri + 8) & (B_ - 1);
    bool dblk = (i0 == j0);
    bool pblk = (j0 == (i0 ^ 512));

    float sv0[4][2], sv1[4][2];       // S values rows lr0 / lr1
    float m0 = 0.f, m1 = 0.f;
#pragma unroll
    for (int nt = 0; nt < 4; nt++) {
        int lc = wn * 32 + nt * 8 + 2 * t4;
        int cj = j0 + lc;
        float nb0 = g_nA[cj];
        float nb1 = g_nA[cj + 1];
        float* dd = dot[nt];
        float d00 = fdist(fmaxf(na0 + nb0 - 2.f * dd[0], 0.f));
        float d01 = fdist(fmaxf(na0 + nb1 - 2.f * dd[1], 0.f));
        float d10 = fdist(fmaxf(na1 + nb0 - 2.f * dd[2], 0.f));
        float d11 = fdist(fmaxf(na1 + nb1 - 2.f * dd[3], 0.f));
        int jm = cj & (B_ - 1);
        float2 af0 = *(const float2*)&g_acc[ri * B_ + jm];
        float2 af1 = *(const float2*)&g_acc[(ri + 8) * B_ + jm];
        float2 bf0 = *(const float2*)&g_accT[im0 * M_ + cj];
        float2 bf1 = *(const float2*)&g_accT[im1 * M_ + cj];
        float q00 = af0.x * af0.x + bf0.x * bf0.x + d00 * d00;
        float q01 = af0.y * af0.y + bf0.y * bf0.y + d01 * d01;
        float q10 = af1.x * af1.x + bf1.x * bf1.x + d10 * d10;
        float q11 = af1.y * af1.y + bf1.y * bf1.y + d11 * d11;
        sv0[nt][0] = q00 * rsq_ap(q00);    // sqrt; q >= d^2 > 200, never 0
        sv0[nt][1] = q01 * rsq_ap(q01);
        sv1[nt][0] = q10 * rsq_ap(q10);
        sv1[nt][1] = q11 * rsq_ap(q11);
        m0 = fmaxf(m0, fmaxf(sv0[nt][0], sv0[nt][1]));
        m1 = fmaxf(m1, fmaxf(sv1[nt][0], sv1[nt][1]));
        if (pblk) {
            if (lc == lr0) g_spos[ri] = sv0[nt][0];
            if (lc + 1 == lr0) g_spos[ri] = sv0[nt][1];
            if (lc == lr1) g_spos[ri + 8] = sv1[nt][0];
            if (lc + 1 == lr1) g_spos[ri + 8] = sv1[nt][1];
        }
    }
    // block-local row max (exact, deterministic)
    m0 = fmaxf(m0, __shfl_xor_sync(0xffffffffu, m0, 1));
    m0 = fmaxf(m0, __shfl_xor_sync(0xffffffffu, m0, 2));
    m1 = fmaxf(m1, __shfl_xor_sync(0xffffffffu, m1, 1));
    m1 = fmaxf(m1, __shfl_xor_sync(0xffffffffu, m1, 2));
    if (t4 == 0) {
        atomicMax(&srmax[lr0], __float_as_int(m0));
        atomicMax(&srmax[lr1], __float_as_int(m1));
    }
    __syncthreads();
    float mr0 = __int_as_float(srmax[lr0]);
    float mr1 = __int_as_float(srmax[lr1]);

    float s0 = 0.f, s1 = 0.f;
#pragma unroll
    for (int nt = 0; nt < 4; nt++) {
        int lc = wn * 32 + nt * 8 + 2 * t4;
        float e00 = __expf(sv0[nt][0] - mr0);
        float e01 = __expf(sv0[nt][1] - mr0);
        float e10 = __expf(sv1[nt][0] - mr1);
        float e11 = __expf(sv1[nt][1] - mr1);
        if (dblk) {                     // exclude diagonal from sum
            if (lc == lr0) e00 = 0.f;
            if (lc + 1 == lr0) e01 = 0.f;
            if (lc == lr1) e10 = 0.f;
            if (lc + 1 == lr1) e11 = 0.f;
        }
        s0 += e00 + e01;
        s1 += e10 + e11;
    }
    // quad reduce (xor tree -> same grouping every run)
    s0 += __shfl_xor_sync(0xffffffffu, s0, 1);
    s0 += __shfl_xor_sync(0xffffffffu, s0, 2);
    s1 += __shfl_xor_sync(0xffffffffu, s1, 1);
    s1 += __shfl_xor_sync(0xffffffffu, s1, 2);
    if (t4 == 0) {
        sps[lr0][wn] = s0;
        sps[lr1][wn] = s1;
    }
    __syncthreads();
    if (tid < 64) {
        g_pm[blockIdx.x * M_ + i0 + tid] = __int_as_float(srmax[tid]);
        g_ps[blockIdx.x * M_ + i0 + tid] = sps[tid][0] + sps[tid][1];
    }
}

// ---------------------------------------------------------------------------
// K4: single-block finish: thread-per-row lse combine, then mean -> out.
__global__ void __launch_bounds__(1024) finish(float* __restrict__ out) {
    int row = threadIdx.x;            // 0..1023
    __shared__ float red[1024];

    // per-row: max over 16 tile maxes (fixed order)
    float M = g_pm[row];
#pragma unroll
    for (int t = 1; t < NJT; t++) M = fmaxf(M, g_pm[t * M_ + row]);
    // partial-sumexp combine (fixed order)
    float p = 0.f;
#pragma unroll
    for (int t = 0; t < NJT; t++)
        p += g_ps[t * M_ + row] * __expf(g_pm[t * M_ + row] - M);
    float loss = -((g_spos[row] - M) - logf(p));

    red[row] = loss;
    __syncthreads();
    for (int st = 512; st > 0; st >>= 1) {
        if (row < st) red[row] += red[row + st];
        __syncthreads();
    }
    if (row == 0) out[0] = red[0] * (1.f / (float)M_);
}

// ---------------------------------------------------------------------------
extern "C" void kernel_launch(void* const* d_in, const int* in_sizes, int n_in,
                              void* d_out, int out_size) {
    const float* features = (const float*)d_in[0];   // (512, 2, 128) f32
    const int*   indices  = (const int*)d_in[1];     // (512,) i32
    const float* saved    = (const float*)d_in[2];   // (100000, 128) f32
    const int*   rks      = (const int*)d_in[3];     // (100000, 50) i32
    float* out = (float*)d_out;

    setup<<<128 + (K_ * B_) / 8, 256>>>(features, saved, indices, rks);
    pk_all<<<dim3(B_ / 64, M_ / 64, 2), 256>>>();
    se_fused<<<dim3(M_ / 64, M_ / 64), 256>>>();
    finish<<<1, 1024>>>(out);
}

// round 15
// speedup vs baseline: 1.1328x; 1.0205x over previous
#include <cuda_runtime.h>
#include <math.h>

// Problem constants
#define B_   512
#define V_   2
#define D_   128
#define M_   1024          // V*B
#define K_   15            // TOP_K
#define KMAX 50
#define INV_T 14.285714285714286f   // 1/0.07
#define NJT  16            // j-tiles in se_fused
#define CM   50.0f         // constant lse shift; S < 49.5 always

// Scratch (static device globals)
__device__ unsigned g_Abf[M_ * 64];        // anchors packed bf16x2 [i][d/2]
__device__ unsigned g_Gbf[K_ * B_ * 64];   // neighbors packed bf16x2
__device__ float g_nA[M_];                 // ||A_i||^2 (fp32 exact)
__device__ float g_nG[K_ * B_];            // ||G_r||^2
__device__ float g_acc[M_ * B_];           // accB (red.add target)
__device__ float g_accT[B_ * M_];          // accB transposed (red.add target)
__device__ float g_ps[NJT * M_];           // per-(jtile,row) partial sum exp(S-CM)
__device__ float g_spos[M_];               // S[i][i^512]
__device__ int   g_ctr;                    // se_fused completion counter

// ---------------------------------------------------------------------------
__device__ __forceinline__ unsigned pack_bf(float lo, float hi) {
    unsigned r;
    asm("cvt.rn.bf16x2.f32 %0, %1, %2;" : "=r"(r) : "f"(hi), "f"(lo));
    return r;
}
__device__ __forceinline__ float rsq_ap(float x) {
    float r; asm("rsqrt.approx.f32 %0, %1;" : "=f"(r) : "f"(x)); return r;
}
__device__ __forceinline__ float rcp_ap(float x) {
    float r; asm("rcp.approx.f32 %0, %1;" : "=f"(r) : "f"(x)); return r;
}
__device__ __forceinline__ float fdist(float sq) {
    float d = (sq > 0.f) ? sq * rsq_ap(sq) : 0.f;   // sqrt(sq) via rsqrt
    return (1.f + rcp_ap(1.f + d)) * INV_T;
}
__device__ __forceinline__ void redadd(float* p, float v) {
    asm volatile("red.global.add.f32 [%0], %1;" :: "l"(p), "f"(v) : "memory");
}
__device__ __forceinline__ void mma_bf16(float c[4], const unsigned a[4],
                                         unsigned b0, unsigned b1) {
    asm volatile(
        "mma.sync.aligned.m16n8k16.row.col.f32.bf16.bf16.f32 "
        "{%0,%1,%2,%3}, {%4,%5,%6,%7}, {%8,%9}, {%0,%1,%2,%3};\n"
        : "+f"(c[0]), "+f"(c[1]), "+f"(c[2]), "+f"(c[3])
        : "r"(a[0]), "r"(a[1]), "r"(a[2]), "r"(a[3]), "r"(b0), "r"(b1));
}
__device__ __forceinline__ void ldsm_x4(unsigned r[4], unsigned addr) {
    asm volatile(
        "ldmatrix.sync.aligned.m8n8.x4.shared.b16 {%0,%1,%2,%3}, [%4];"
        : "=r"(r[0]), "=r"(r[1]), "=r"(r[2]), "=r"(r[3]) : "r"(addr));
}
__device__ __forceinline__ unsigned sm_u32(const void* p) {
    return (unsigned)__cvta_generic_to_shared(p);
}

// ---------------------------------------------------------------------------
// K1: merged setup. Blocks 0..127: anchors + zero acc targets (+ctr reset).
// Blocks 128..1087: neighbor gather. Warp-per-row both halves.
__global__ void __launch_bounds__(256) setup(const float* __restrict__ features,
                                             const float* __restrict__ saved,
                                             const int* __restrict__ indices,
                                             const int* __restrict__ rks) {
    int w = threadIdx.x >> 5;
    int lane = threadIdx.x & 31;

    if (blockIdx.x < 128) {
        int i = blockIdx.x * 8 + w;          // anchor row
        int v = i >> 9;
        int b = i & (B_ - 1);
        float4 val = *(const float4*)&features[(b * V_ + v) * D_ + lane * 4];
        float s = val.x * val.x + val.y * val.y + val.z * val.z + val.w * val.w;
#pragma unroll
        for (int st = 16; st > 0; st >>= 1)
            s += __shfl_xor_sync(0xffffffffu, s, st);
        *(uint2*)&g_Abf[i * 64 + lane * 2] =
            make_uint2(pack_bf(val.x, val.y), pack_bf(val.z, val.w));
        if (lane == 0) g_nA[i] = s;
        if (blockIdx.x == 0 && threadIdx.x == 0) g_ctr = 0;

        // zero reduction targets: 131072 float4 each; 32768 lanes -> 4 each
        int t = blockIdx.x * 256 + threadIdx.x;
        float4 z = make_float4(0.f, 0.f, 0.f, 0.f);
#pragma unroll
        for (int q = 0; q < 4; q++) {
            ((float4*)g_acc)[q * 32768 + t] = z;
            ((float4*)g_accT)[q * 32768 + t] = z;
        }
    } else {
        int r = (blockIdx.x - 128) * 8 + w;  // neighbor row 0..K_*B_-1
        int k = r / B_;
        int b = r - k * B_;
        int idx = rks[indices[b] * KMAX + k];
        float4 val = *(const float4*)&saved[(long long)idx * D_ + lane * 4];
        float s = val.x * val.x + val.y * val.y + val.z * val.z + val.w * val.w;
#pragma unroll
        for (int st = 16; st > 0; st >>= 1)
            s += __shfl_xor_sync(0xffffffffu, s, st);
        *(uint2*)&g_Gbf[r * 64 + lane * 2] =
            make_uint2(pack_bf(val.x, val.y), pack_bf(val.z, val.w));
        if (lane == 0) g_nG[r] = s;
    }
}

// ---------------------------------------------------------------------------
// K2: partial accB over a k-group, red.add'ed (pre-scaled by 1/15) into
// g_acc/g_accT. Exactly 2 contributions per address onto 0.0 -> deterministic.
__global__ void __launch_bounds__(256, 2) pk_all() {
    __shared__ unsigned As[64 * 64];
    __shared__ unsigned Bs[2][64 * 64];

    int grp = blockIdx.z;
    int k0 = grp * 8;
    int kend = (grp == 0) ? 8 : K_;
    int i0 = blockIdx.y * 64;
    int b0 = blockIdx.x * 64;
    int tid = threadIdx.x;
    int lane = tid & 31, warp = tid >> 5;
    int wm = warp >> 1, wn = warp & 1;
    int g = lane >> 2, t4 = lane & 3;
    int l7 = lane & 7;

#pragma unroll
    for (int q = 0; q < 4; q++) {
        int idx = q * 256 + tid;
        int row = idx >> 4, c4 = idx & 15;
        uint4 v = *(const uint4*)&g_Abf[(i0 + row) * 64 + c4 * 4];
        *(uint4*)&As[row * 64 + ((c4 * 4) ^ ((row & 7) << 2))] = v;
    }

    unsigned swl = l7 << 2;
    unsigned aBase = sm_u32(As) + (wm * 16 + (lane & 15)) * 256;
    unsigned koA = (lane >> 4) << 2;
    unsigned bRow0 = wn * 32 + ((lane >> 4) & 1) * 8 + l7;
    unsigned koB = ((lane >> 3) & 1) << 2;
    unsigned bBase0 = sm_u32(Bs) + bRow0 * 256;
    unsigned bBase1 = bBase0 + 16 * 256;

    float fsum[4][4];
#pragma unroll
    for (int nt = 0; nt < 4; nt++)
#pragma unroll
        for (int q = 0; q < 4; q++) fsum[nt][q] = 0.f;

    uint4 pre[4];
    {
        const unsigned* Gb = g_Gbf + (k0 * B_ + b0) * 64;
#pragma unroll
        for (int q = 0; q < 4; q++) {
            int idx = q * 256 + tid;
            int row = idx >> 4, c4 = idx & 15;
            pre[q] = *(const uint4*)&Gb[row * 64 + c4 * 4];
        }
    }

    int cur = 0;
#pragma unroll 1
    for (int k = k0; k < kend; k++) {
#pragma unroll
        for (int q = 0; q < 4; q++) {
            int idx = q * 256 + tid;
            int row = idx >> 4, c4 = idx & 15;
            *(uint4*)&Bs[cur][row * 64 + ((c4 * 4) ^ ((row & 7) << 2))] = pre[q];
        }
        __syncthreads();

        if (k + 1 < kend) {
            const unsigned* Gb = g_Gbf + ((k + 1) * B_ + b0) * 64;
#pragma unroll
            for (int q = 0; q < 4; q++) {
                int idx = q * 256 + tid;
                int row = idx >> 4, c4 = idx & 15;
                pre[q] = *(const uint4*)&Gb[row * 64 + c4 * 4];
            }
        }

        float dot[4][4];
#pragma unroll
        for (int nt = 0; nt < 4; nt++)
#pragma unroll
            for (int q = 0; q < 4; q++) dot[nt][q] = 0.f;

        unsigned bcur = (unsigned)(cur * (64 * 64 * 4));
#pragma unroll
        for (int s = 0; s < 8; s++) {
            unsigned a[4], bb0[4], bb1[4];
            ldsm_x4(a, aBase + ((((unsigned)(s * 8) + koA) ^ swl) << 2));
            ldsm_x4(bb0, bBase0 + bcur + ((((unsigned)(s * 8) + koB) ^ swl) << 2));
            ldsm_x4(bb1, bBase1 + bcur + ((((unsigned)(s * 8) + koB) ^ swl) << 2));
            mma_bf16(dot[0], a, bb0[0], bb0[1]);
            mma_bf16(dot[1], a, bb0[2], bb0[3]);
            mma_bf16(dot[2], a, bb1[0], bb1[1]);
            mma_bf16(dot[3], a, bb1[2], bb1[3]);
        }

        int ri = i0 + wm * 16 + g;
        float na0 = g_nA[ri];
        float na1 = g_nA[ri + 8];
#pragma unroll
        for (int nt = 0; nt < 4; nt++) {
            int cb = b0 + wn * 32 + nt * 8 + 2 * t4;
            float ng0 = g_nG[k * B_ + cb];
            float ng1 = g_nG[k * B_ + cb + 1];
            float* dd = dot[nt];
            fsum[nt][0] += fdist(fmaxf(na0 + ng0 - 2.f * dd[0], 0.f));
            fsum[nt][1] += fdist(fmaxf(na0 + ng1 - 2.f * dd[1], 0.f));
            fsum[nt][2] += fdist(fmaxf(na1 + ng0 - 2.f * dd[2], 0.f));
            fsum[nt][3] += fdist(fmaxf(na1 + ng1 - 2.f * dd[3], 0.f));
        }
        cur ^= 1;
    }

    const float inv = 1.f / (float)K_;
    int ri = i0 + wm * 16 + g;
#pragma unroll
    for (int nt = 0; nt < 4; nt++) {
        int cb = b0 + wn * 32 + nt * 8 + 2 * t4;
        float v00 = fsum[nt][0] * inv, v01 = fsum[nt][1] * inv;
        float v10 = fsum[nt][2] * inv, v11 = fsum[nt][3] * inv;
        redadd(&g_acc[ri * B_ + cb], v00);
        redadd(&g_acc[ri * B_ + cb + 1], v01);
        redadd(&g_acc[(ri + 8) * B_ + cb], v10);
        redadd(&g_acc[(ri + 8) * B_ + cb + 1], v11);
        redadd(&g_accT[cb * M_ + ri], v00);
        redadd(&g_accT[(cb + 1) * M_ + ri], v01);
        redadd(&g_accT[cb * M_ + ri + 8], v10);
        redadd(&g_accT[(cb + 1) * M_ + ri + 8], v11);
    }
}

// ---------------------------------------------------------------------------
// K3: fused S + constant-shift sumexp partials + last-block finish.
// Tile 64(i) x 64(j). exp(S - CM) is always in (e^-25, e^-0.5): safe.
__global__ void __launch_bounds__(256, 2) se_fused(float* __restrict__ out) {
    __shared__ unsigned As[64 * 64];
    __shared__ unsigned Bs[64 * 64];
    __shared__ float sps[64][2];
    __shared__ float red[256];
    __shared__ int slast;

    int i0 = blockIdx.y * 64;
    int j0 = blockIdx.x * 64;
    int tid = threadIdx.x;
    int lane = tid & 31, warp = tid >> 5;
    int wm = warp >> 1, wn = warp & 1;
    int g = lane >> 2, t4 = lane & 3;
    int l7 = lane & 7;

#pragma unroll
    for (int q = 0; q < 4; q++) {
        int idx = q * 256 + tid;
        int row = idx >> 4, c4 = idx & 15;
        uint4 va = *(const uint4*)&g_Abf[(i0 + row) * 64 + c4 * 4];
        *(uint4*)&As[row * 64 + ((c4 * 4) ^ ((row & 7) << 2))] = va;
        uint4 vb = *(const uint4*)&g_Abf[(j0 + row) * 64 + c4 * 4];
        *(uint4*)&Bs[row * 64 + ((c4 * 4) ^ ((row & 7) << 2))] = vb;
    }
    __syncthreads();

    unsigned swl = l7 << 2;
    unsigned aBase = sm_u32(As) + (wm * 16 + (lane & 15)) * 256;
    unsigned koA = (lane >> 4) << 2;
    unsigned bRow0 = wn * 32 + ((lane >> 4) & 1) * 8 + l7;
    unsigned koB = ((lane >> 3) & 1) << 2;
    unsigned bBase0 = sm_u32(Bs) + bRow0 * 256;
    unsigned bBase1 = bBase0 + 16 * 256;

    float dot[4][4];
#pragma unroll
    for (int nt = 0; nt < 4; nt++)
#pragma unroll
        for (int q = 0; q < 4; q++) dot[nt][q] = 0.f;

#pragma unroll
    for (int s = 0; s < 8; s++) {
        unsigned a[4], bb0[4], bb1[4];
        ldsm_x4(a, aBase + ((((unsigned)(s * 8) + koA) ^ swl) << 2));
        ldsm_x4(bb0, bBase0 + ((((unsigned)(s * 8) + koB) ^ swl) << 2));
        ldsm_x4(bb1, bBase1 + ((((unsigned)(s * 8) + koB) ^ swl) << 2));
        mma_bf16(dot[0], a, bb0[0], bb0[1]);
        mma_bf16(dot[1], a, bb0[2], bb0[3]);
        mma_bf16(dot[2], a, bb1[0], bb1[1]);
        mma_bf16(dot[3], a, bb1[2], bb1[3]);
    }

    int lr0 = wm * 16 + g;            // local rows
    int lr1 = lr0 + 8;
    int ri = i0 + lr0;
    float na0 = g_nA[ri];
    float na1 = g_nA[ri + 8];
    int im0 = ri & (B_ - 1);
    int im1 = (ri + 8) & (B_ - 1);
    bool dblk = (i0 == j0);
    bool pblk = (j0 == (i0 ^ 512));

    float s0 = 0.f, s1 = 0.f;
#pragma unroll
    for (int nt = 0; nt < 4; nt++) {
        int lc = wn * 32 + nt * 8 + 2 * t4;
        int cj = j0 + lc;
        float nb0 = g_nA[cj];
        float nb1 = g_nA[cj + 1];
        float* dd = dot[nt];
        float d00 = fdist(fmaxf(na0 + nb0 - 2.f * dd[0], 0.f));
        float d01 = fdist(fmaxf(na0 + nb1 - 2.f * dd[1], 0.f));
        float d10 = fdist(fmaxf(na1 + nb0 - 2.f * dd[2], 0.f));
        float d11 = fdist(fmaxf(na1 + nb1 - 2.f * dd[3], 0.f));
        int jm = cj & (B_ - 1);
        float2 af0 = *(const float2*)&g_acc[ri * B_ + jm];
        float2 af1 = *(const float2*)&g_acc[(ri + 8) * B_ + jm];
        float2 bf0 = *(const float2*)&g_accT[im0 * M_ + cj];
        float2 bf1 = *(const float2*)&g_accT[im1 * M_ + cj];
        float q00 = af0.x * af0.x + bf0.x * bf0.x + d00 * d00;
        float q01 = af0.y * af0.y + bf0.y * bf0.y + d01 * d01;
        float q10 = af1.x * af1.x + bf1.x * bf1.x + d10 * d10;
        float q11 = af1.y * af1.y + bf1.y * bf1.y + d11 * d11;
        float v00 = q00 * rsq_ap(q00);     // sqrt; q >= d^2 > 200, never 0
        float v01 = q01 * rsq_ap(q01);
        float v10 = q10 * rsq_ap(q10);
        float v11 = q11 * rsq_ap(q11);
        if (pblk) {
            if (lc == lr0) g_spos[ri] = v00;
            if (lc + 1 == lr0) g_spos[ri] = v01;
            if (lc == lr1) g_spos[ri + 8] = v10;
            if (lc + 1 == lr1) g_spos[ri + 8] = v11;
        }
        float e00 = __expf(v00 - CM);
        float e01 = __expf(v01 - CM);
        float e10 = __expf(v10 - CM);
        float e11 = __expf(v11 - CM);
        if (dblk) {                     // exclude diagonal from sum
            if (lc == lr0) e00 = 0.f;
            if (lc + 1 == lr0) e01 = 0.f;
            if (lc == lr1) e10 = 0.f;
            if (lc + 1 == lr1) e11 = 0.f;
        }
        s0 += e00 + e01;
        s1 += e10 + e11;
    }
    // quad reduce (xor tree -> same grouping every run)
    s0 += __shfl_xor_sync(0xffffffffu, s0, 1);
    s0 += __shfl_xor_sync(0xffffffffu, s0, 2);
    s1 += __shfl_xor_sync(0xffffffffu, s1, 1);
    s1 += __shfl_xor_sync(0xffffffffu, s1, 2);
    if (t4 == 0) {
        sps[lr0][wn] = s0;
        sps[lr1][wn] = s1;
    }
    __syncthreads();
    if (tid < 64)
        g_ps[blockIdx.x * M_ + i0 + tid] = sps[tid][0] + sps[tid][1];

    // ---- last-block finish ----
    __threadfence();
    __syncthreads();
    if (tid == 0) slast = (atomicAdd(&g_ctr, 1) == NJT * NJT - 1);
    __syncthreads();
    if (!slast) return;

    float lsum = 0.f;
#pragma unroll
    for (int q = 0; q < 4; q++) {
        int row = q * 256 + tid;
        float p = 0.f;
#pragma unroll
        for (int t = 0; t < NJT; t++) p += g_ps[t * M_ + row];
        lsum += -((g_spos[row] - CM) - logf(p));
    }
    red[tid] = lsum;
    __syncthreads();
    for (int st = 128; st > 0; st >>= 1) {
        if (tid < st) red[tid] += red[tid + st];
        __syncthreads();
    }
    if (tid == 0) out[0] = red[0] * (1.f / (float)M_);
}

// ---------------------------------------------------------------------------
extern "C" void kernel_launch(void* const* d_in, const int* in_sizes, int n_in,
                              void* d_out, int out_size) {
    const float* features = (const float*)d_in[0];   // (512, 2, 128) f32
    const int*   indices  = (const int*)d_in[1];     // (512,) i32
    const float* saved    = (const float*)d_in[2];   // (100000, 128) f32
    const int*   rks      = (const int*)d_in[3];     // (100000, 50) i32
    float* out = (float*)d_out;

    setup<<<128 + (K_ * B_) / 8, 256>>>(features, saved, indices, rks);
    pk_all<<<dim3(B_ / 64, M_ / 64, 2), 256>>>();
    se_fused<<<dim3(M_ / 64, M_ / 64), 256>>>(out);
}